// round 5
// baseline (speedup 1.0000x reference)
#include <cuda_runtime.h>
#include <math.h>

// ---------------------------------------------------------------------------
// EMG_SyEMB fused kernel, sm_103a.
// One block = (batch b, 40-patch tile = 1000 timesteps). Everything staged in
// shared memory; single pass over HBM inputs, single write of outputs.
// Pure fp32 math. S (synergy signal) is zero-padded outside [0,T) to match
// the reference's conv padding semantics (NOT evaluated in the halo).
// ---------------------------------------------------------------------------

namespace {
constexpr int B_ = 64, T_ = 50000, C_ = 4, D_ = 160, P_ = 25, L_ = 2000;
constexpr int TILE   = 1000;           // timesteps per block
constexpr int NPATCH = TILE / P_;      // 40
constexpr int HALO   = 16;             // 4 (dw K9) + 12 (env K25)
constexpr int XLEN   = TILE + 2*HALO;  // 1032
constexpr int S0LEN  = TILE + 8;       // 1008 (dw K9 halo = 4 each side)
constexpr int NTH    = 512;
constexpr int TPB    = L_ / NPATCH;    // 50 tiles per batch
constexpr int WPAD   = 161;            // w_proj smem stride over d
constexpr int PPAD   = 41;             // xs smem stride over p

// shared memory layout (float offsets)
constexpr int OFF_SX   = 0;                         // x = X*M     [4][1032]
constexpr int OFF_AX   = OFF_SX  + 4*XLEN;          // |x|         [4][1032]
constexpr int OFF_ADX  = OFF_AX  + 4*XLEN;          // |dx|        [4][1032]
constexpr int OFF_S0   = OFF_ADX + 4*XLEN;          // W@xm        [4][1008]
constexpr int OFF_SM   = OFF_S0  + 4*S0LEN;         // Sm          [1000][4]
constexpr int OFF_XS   = OFF_SM  + TILE*4;          // xs          [100][41]
constexpr int OFF_H    = OFF_XS  + 100*PPAD;        // patch-conv out [40][160]
constexpr int OFF_WS   = OFF_H   + NPATCH*D_;       // w_proj^T    [100][161]
constexpr int OFF_WENV = OFF_WS  + 100*WPAD;        // [4][25]
constexpr int OFF_WBUR = OFF_WENV + 100;            // [4][9]
constexpr int OFF_WDW  = OFF_WBUR + 36;             // [4][9]
constexpr int OFF_WPW  = OFF_WDW  + 36;             // [4][4]
constexpr int OFF_WN   = OFF_WPW  + 16;             // normalized synergy W [4][4]
constexpr int OFF_G    = OFF_WN   + 16;             // ln_gamma [160]
constexpr int OFF_BT   = OFF_G    + D_;             // ln_beta  [160]
constexpr int SMEM_FLOATS = OFF_BT + D_;            // 47540 floats = 190160 B
}

__device__ __forceinline__ float gelu_(float x) {
    return 0.5f * x * (1.0f + erff(x * 0.70710678118654752440f));
}

__global__ void __launch_bounds__(NTH, 1)
emg_fused_kernel(const float* __restrict__ X,  const float* __restrict__ Mk,
                 const float* __restrict__ w_env, const float* __restrict__ w_bur,
                 const float* __restrict__ syn,   const float* __restrict__ w_dw,
                 const float* __restrict__ w_pw,  const float* __restrict__ w_proj,
                 const float* __restrict__ gam,   const float* __restrict__ bet,
                 float* __restrict__ out_h, float* __restrict__ out_mp)
{
    extern __shared__ float smem[];
    const int tid  = threadIdx.x;
    const int b    = blockIdx.x / TPB;
    const int tile = blockIdx.x % TPB;
    const int t0   = tile * TILE;

    // ---- load weights into smem ------------------------------------------
    for (int i = tid; i < D_ * 100; i += NTH) {
        int d = i / 100, k = i - d * 100;
        smem[OFF_WS + k * WPAD + d] = w_proj[i];
    }
    for (int i = tid; i < 100; i += NTH) smem[OFF_WENV + i] = w_env[i];
    for (int i = tid; i < 36;  i += NTH) smem[OFF_WBUR + i] = w_bur[i];
    for (int i = tid; i < 36;  i += NTH) smem[OFF_WDW  + i] = w_dw[i];
    for (int i = tid; i < 16;  i += NTH) smem[OFF_WPW  + i] = w_pw[i];
    for (int i = tid; i < D_;  i += NTH) { smem[OFF_G + i] = gam[i]; smem[OFF_BT + i] = bet[i]; }
    if (tid == 0) {
        // W = softplus(syn); rows normalized over c (sum clamped at 1e-6)
        float sp[16];
        for (int m = 0; m < 4; m++) {
            float s = 0.f;
            for (int c = 0; c < 4; c++) {
                float x = syn[m * 4 + c];
                float v = (x > 20.f) ? x : log1pf(expf(x));
                sp[m * 4 + c] = v; s += v;
            }
            float inv = 1.f / fmaxf(s, 1e-6f);
            for (int c = 0; c < 4; c++) smem[OFF_WN + m * 4 + c] = sp[m * 4 + c] * inv;
        }
    }
    __syncthreads();

    // ---- phase 1: x = X*M (with halo), Sm = clip(W@(M>0),0,1) ------------
    const float4* Xb = reinterpret_cast<const float4*>(X)  + (size_t)b * T_;
    const float4* Mb = reinterpret_cast<const float4*>(Mk) + (size_t)b * T_;
    for (int tt = tid; tt < XLEN; tt += NTH) {
        int g = t0 - HALO + tt;
        float x0 = 0.f, x1 = 0.f, x2 = 0.f, x3 = 0.f;
        if ((unsigned)g < (unsigned)T_) {
            float4 xv = Xb[g];
            float4 mv = Mb[g];
            x0 = xv.x * mv.x; x1 = xv.y * mv.y; x2 = xv.z * mv.z; x3 = xv.w * mv.w;
            int u = tt - HALO;
            if ((unsigned)u < (unsigned)TILE) {
                float m0 = mv.x > 0.f ? 1.f : 0.f, m1 = mv.y > 0.f ? 1.f : 0.f;
                float m2 = mv.z > 0.f ? 1.f : 0.f, m3 = mv.w > 0.f ? 1.f : 0.f;
                float4 s;
                s.x = fminf(fmaxf(smem[OFF_WN+ 0]*m0 + smem[OFF_WN+ 1]*m1 + smem[OFF_WN+ 2]*m2 + smem[OFF_WN+ 3]*m3, 0.f), 1.f);
                s.y = fminf(fmaxf(smem[OFF_WN+ 4]*m0 + smem[OFF_WN+ 5]*m1 + smem[OFF_WN+ 6]*m2 + smem[OFF_WN+ 7]*m3, 0.f), 1.f);
                s.z = fminf(fmaxf(smem[OFF_WN+ 8]*m0 + smem[OFF_WN+ 9]*m1 + smem[OFF_WN+10]*m2 + smem[OFF_WN+11]*m3, 0.f), 1.f);
                s.w = fminf(fmaxf(smem[OFF_WN+12]*m0 + smem[OFF_WN+13]*m1 + smem[OFF_WN+14]*m2 + smem[OFF_WN+15]*m3, 0.f), 1.f);
                reinterpret_cast<float4*>(smem + OFF_SM)[u] = s;
            }
        }
        smem[OFF_SX + 0*XLEN + tt] = x0;
        smem[OFF_SX + 1*XLEN + tt] = x1;
        smem[OFF_SX + 2*XLEN + tt] = x2;
        smem[OFF_SX + 3*XLEN + tt] = x3;
    }
    __syncthreads();

    // ---- phase 1b: |x| and |dx| (dx[0]=0, zero outside [0,T)) ------------
    for (int i = tid; i < 4 * XLEN; i += NTH) {
        int c = i / XLEN, tt = i - c * XLEN;
        int g = t0 - HALO + tt;
        float xv = smem[OFF_SX + c*XLEN + tt];
        smem[OFF_AX + c*XLEN + tt] = fabsf(xv);
        float v = 0.f;
        if (tt >= 1 && g >= 1 && g < T_)
            v = fabsf(xv - smem[OFF_SX + c*XLEN + tt - 1]);
        smem[OFF_ADX + c*XLEN + tt] = v;
    }
    __syncthreads();

    // ---- phase 2+3: xm = .9 env + .6 burst + .2 x ; S0 = W @ xm ----------
    // local j covers global t in [t0-4, t0+TILE+4).
    // CRITICAL: the reference zero-pads S for the K9 dwconv — S0 must be 0
    // for global t outside [0,T), NOT evaluated from the (nonzero) env halo.
    for (int j = tid; j < S0LEN; j += NTH) {
        const int tg = t0 - 4 + j;
        const bool tvalid = (unsigned)tg < (unsigned)T_;
        float s0 = 0.f, s1 = 0.f, s2 = 0.f, s3 = 0.f;
        if (tvalid) {
            #pragma unroll
            for (int c = 0; c < 4; c++) {
                const float* xc = smem + OFF_SX  + c * XLEN;
                const float* ax = smem + OFF_AX  + c * XLEN;
                const float* ac = smem + OFF_ADX + c * XLEN;
                const float* we = smem + OFF_WENV + c * 25;
                const float* wb = smem + OFF_WBUR + c * 9;
                float env = 0.f;
                #pragma unroll
                for (int k = 0; k < 25; k++) env = fmaf(ax[j + k], we[k], env);
                float bur = 0.f;
                #pragma unroll
                for (int k = 0; k < 9; k++)  bur = fmaf(ac[j + 8 + k], wb[k], bur);
                float xm = 0.9f * env + 0.6f * bur + 0.2f * xc[j + 12];
                s0 = fmaf(smem[OFF_WN +  0 + c], xm, s0);
                s1 = fmaf(smem[OFF_WN +  4 + c], xm, s1);
                s2 = fmaf(smem[OFF_WN +  8 + c], xm, s2);
                s3 = fmaf(smem[OFF_WN + 12 + c], xm, s3);
            }
        }
        smem[OFF_S0 + 0*S0LEN + j] = s0;
        smem[OFF_S0 + 1*S0LEN + j] = s1;
        smem[OFF_S0 + 2*S0LEN + j] = s2;
        smem[OFF_S0 + 3*S0LEN + j] = s3;
    }
    __syncthreads();

    // ---- phase 4: dwconv K9 + gelu, pointwise 4x4 + gelu, gate by Sm -----
    for (int u = tid; u < TILE; u += NTH) {
        float g1[4];
        #pragma unroll
        for (int m = 0; m < 4; m++) {
            const float* s0p = smem + OFF_S0 + m * S0LEN + u;
            const float* wd  = smem + OFF_WDW + m * 9;
            float a = 0.f;
            #pragma unroll
            for (int k = 0; k < 9; k++) a = fmaf(s0p[k], wd[k], a);
            g1[m] = gelu_(a);
        }
        float4 smv = reinterpret_cast<const float4*>(smem + OFF_SM)[u];
        float sarr[4] = {smv.x, smv.y, smv.z, smv.w};
        int p = u / 25, jj = u - p * 25;
        #pragma unroll
        for (int o = 0; o < 4; o++) {
            float a = smem[OFF_WPW + o*4 + 0] * g1[0] + smem[OFF_WPW + o*4 + 1] * g1[1]
                    + smem[OFF_WPW + o*4 + 2] * g1[2] + smem[OFF_WPW + o*4 + 3] * g1[3];
            float xs = gelu_(a) * sarr[o];
            // GEMM layout [k = o*25+jj][p], stride 41
            smem[OFF_XS + (o * 25 + jj) * PPAD + p] = xs;
        }
    }
    __syncthreads();

    // ---- phase 5: patch conv GEMM h[p][d] = sum_k xs[k][p] * wT[k][d] ----
    // 200 threads, each computes 4 d (stride 40) x 8 p.
    if (tid < 200) {
        const int d0    = tid % 40;
        const int pbase = (tid / 40) * 8;
        float acc[8][4];
        #pragma unroll
        for (int j = 0; j < 8; j++)
            #pragma unroll
            for (int i = 0; i < 4; i++) acc[j][i] = 0.f;
        const float* ws = smem + OFF_WS;
        const float* xs = smem + OFF_XS;
        #pragma unroll 4
        for (int k = 0; k < 100; k++) {
            float w0 = ws[k * WPAD + d0];
            float w1 = ws[k * WPAD + d0 + 40];
            float w2 = ws[k * WPAD + d0 + 80];
            float w3 = ws[k * WPAD + d0 + 120];
            #pragma unroll
            for (int j = 0; j < 8; j++) {
                float xv = xs[k * PPAD + pbase + j];
                acc[j][0] = fmaf(xv, w0, acc[j][0]);
                acc[j][1] = fmaf(xv, w1, acc[j][1]);
                acc[j][2] = fmaf(xv, w2, acc[j][2]);
                acc[j][3] = fmaf(xv, w3, acc[j][3]);
            }
        }
        #pragma unroll
        for (int j = 0; j < 8; j++)
            #pragma unroll
            for (int i = 0; i < 4; i++)
                smem[OFF_H + (pbase + j) * D_ + d0 + 40 * i] = acc[j][i];
    }
    __syncthreads();

    // ---- phase 6: LayerNorm over D=160 + m_patch, write outputs ----------
    const int wid = tid >> 5, lane = tid & 31;
    for (int p = wid; p < NPATCH; p += NTH / 32) {
        const float* hp = smem + OFF_H + p * D_;
        float s = 0.f;
        #pragma unroll
        for (int i = 0; i < 5; i++) s += hp[lane + 32 * i];
        #pragma unroll
        for (int o = 16; o; o >>= 1) s += __shfl_xor_sync(0xffffffffu, s, o);
        float mu = s * (1.f / 160.f);
        float v = 0.f;
        #pragma unroll
        for (int i = 0; i < 5; i++) { float d = hp[lane + 32 * i] - mu; v = fmaf(d, d, v); }
        #pragma unroll
        for (int o = 16; o; o >>= 1) v += __shfl_xor_sync(0xffffffffu, v, o);
        float rstd = rsqrtf(v * (1.f / 160.f) + 1e-5f);
        const int pg = tile * NPATCH + p;
        float* oh = out_h + ((size_t)b * L_ + pg) * D_;
        #pragma unroll
        for (int i = 0; i < 5; i++) {
            int d = lane + 32 * i;
            oh[d] = (hp[d] - mu) * rstd * smem[OFF_G + d] + smem[OFF_BT + d];
        }
        // m_patch: m_time[t] = (mean_m Sm > 0) ; patch mean > 0.1
        int pred = 0;
        if (lane < 25) {
            float4 q = reinterpret_cast<const float4*>(smem + OFF_SM)[p * 25 + lane];
            pred = (q.x + q.y + q.z + q.w) > 0.f ? 1 : 0;
        }
        unsigned bal = __ballot_sync(0xffffffffu, pred);
        if (lane == 0) {
            int cnt = __popc(bal & 0x1ffffffu);
            out_mp[(size_t)b * L_ + pg] = ((float)cnt * (1.f / 25.f) > 0.1f) ? 1.f : 0.f;
        }
    }
}

extern "C" void kernel_launch(void* const* d_in, const int* in_sizes, int n_in,
                              void* d_out, int out_size) {
    const float* X      = (const float*)d_in[0];
    const float* M      = (const float*)d_in[1];
    const float* w_env  = (const float*)d_in[2];
    const float* w_bur  = (const float*)d_in[3];
    const float* syn    = (const float*)d_in[4];
    const float* w_dw   = (const float*)d_in[5];
    const float* w_pw   = (const float*)d_in[6];
    const float* w_proj = (const float*)d_in[7];
    const float* gam    = (const float*)d_in[8];
    const float* bet    = (const float*)d_in[9];

    float* out_h  = (float*)d_out;
    float* out_mp = out_h + (size_t)B_ * L_ * D_;

    cudaFuncSetAttribute(emg_fused_kernel,
                         cudaFuncAttributeMaxDynamicSharedMemorySize,
                         SMEM_FLOATS * (int)sizeof(float));

    emg_fused_kernel<<<B_ * TPB, NTH, SMEM_FLOATS * (int)sizeof(float)>>>(
        X, M, w_env, w_bur, syn, w_dw, w_pw, w_proj, gam, bet, out_h, out_mp);
}

// round 6
// speedup vs baseline: 1.0850x; 1.0850x over previous
#include <cuda_runtime.h>
#include <math.h>

// ---------------------------------------------------------------------------
// EMG_SyEMB fused kernel, sm_103a. R6: balanced phases + vectorized/packed GEMM.
// One block = (batch b, 40-patch tile = 1000 timesteps).
// ---------------------------------------------------------------------------

namespace {
constexpr int B_ = 64, T_ = 50000, C_ = 4, D_ = 160, P_ = 25, L_ = 2000;
constexpr int TILE   = 1000;
constexpr int NPATCH = TILE / P_;      // 40
constexpr int HALO   = 16;
constexpr int XLEN   = TILE + 2*HALO;  // 1032
constexpr int S0LEN  = TILE + 8;       // 1008
constexpr int NTH    = 512;
constexpr int TPB    = L_ / NPATCH;    // 50
constexpr int WPADW  = 164;            // WS row stride (d), %4==0 for float4
constexpr int PPAD   = 42;             // XS row stride (p), %2==0 for float2

constexpr int OFF_SX   = 0;                      // [4][1032]
constexpr int OFF_AX   = OFF_SX  + 4*XLEN;       // [4][1032]
constexpr int OFF_ADX  = OFF_AX  + 4*XLEN;       // [4][1032]
constexpr int OFF_S0   = OFF_ADX + 4*XLEN;       // [4][1008]
constexpr int OFF_SM   = OFF_S0  + 4*S0LEN;      // [1000][4]
constexpr int OFF_XS   = OFF_SM  + TILE*4;       // [100][42]
constexpr int OFF_H    = OFF_XS  + 100*PPAD;     // [40][160]
constexpr int OFF_WS   = OFF_H   + NPATCH*D_;    // [100][164]
constexpr int OFF_WENV = OFF_WS  + 100*WPADW;    // [4][25]
constexpr int OFF_WBUR = OFF_WENV + 100;         // [4][9]
constexpr int OFF_WDW  = OFF_WBUR + 36;          // [4][9]
constexpr int OFF_WPW  = OFF_WDW  + 36;          // [4][4]
constexpr int OFF_WN   = OFF_WPW  + 16;          // [4][4]
constexpr int OFF_G    = OFF_WN   + 16;          // [160]
constexpr int OFF_BT   = OFF_G    + D_;          // [160]
constexpr int SMEM_FLOATS = OFF_BT + D_;         // ~47940 floats = ~191.8 KB
}

__device__ __forceinline__ float gelu_(float x) {
    return 0.5f * x * (1.0f + erff(x * 0.70710678118654752440f));
}

// packed fp32x2 helpers (sm_103a FFMA2 — only reachable via PTX)
__device__ __forceinline__ void fma2_(unsigned long long& d,
                                      unsigned long long a, unsigned long long b) {
    asm("fma.rn.f32x2 %0, %1, %2, %0;" : "+l"(d) : "l"(a), "l"(b));
}
__device__ __forceinline__ unsigned long long pk2_(float lo, float hi) {
    unsigned long long r;
    asm("mov.b64 %0, {%1, %2};" : "=l"(r) : "f"(lo), "f"(hi));
    return r;
}
__device__ __forceinline__ float2 upk2_(unsigned long long v) {
    float2 r;
    asm("mov.b64 {%0, %1}, %2;" : "=f"(r.x), "=f"(r.y) : "l"(v));
    return r;
}

__global__ void __launch_bounds__(NTH, 1)
emg_fused_kernel(const float* __restrict__ X,  const float* __restrict__ Mk,
                 const float* __restrict__ w_env, const float* __restrict__ w_bur,
                 const float* __restrict__ syn,   const float* __restrict__ w_dw,
                 const float* __restrict__ w_pw,  const float* __restrict__ w_proj,
                 const float* __restrict__ gam,   const float* __restrict__ bet,
                 float* __restrict__ out_h, float* __restrict__ out_mp)
{
    extern __shared__ float smem[];
    const int tid  = threadIdx.x;
    const int b    = blockIdx.x / TPB;
    const int tile = blockIdx.x % TPB;
    const int t0   = tile * TILE;

    // ---- weights to smem --------------------------------------------------
    // w_proj (D,100) -> WS[k][d], stride 164 (4-way store conflict, one-time)
    for (int i = tid; i < D_ * 100; i += NTH) {
        int d = i / 100, k = i - d * 100;
        smem[OFF_WS + k * WPADW + d] = w_proj[i];
    }
    for (int i = tid; i < 100; i += NTH) smem[OFF_WENV + i] = w_env[i];
    for (int i = tid; i < 36;  i += NTH) smem[OFF_WBUR + i] = w_bur[i];
    for (int i = tid; i < 36;  i += NTH) smem[OFF_WDW  + i] = w_dw[i];
    for (int i = tid; i < 16;  i += NTH) smem[OFF_WPW  + i] = w_pw[i];
    for (int i = tid; i < D_;  i += NTH) { smem[OFF_G + i] = gam[i]; smem[OFF_BT + i] = bet[i]; }
    if (tid == 0) {
        float sp[16];
        for (int m = 0; m < 4; m++) {
            float s = 0.f;
            for (int c = 0; c < 4; c++) {
                float x = syn[m * 4 + c];
                float v = (x > 20.f) ? x : log1pf(expf(x));
                sp[m * 4 + c] = v; s += v;
            }
            float inv = 1.f / fmaxf(s, 1e-6f);
            for (int c = 0; c < 4; c++) smem[OFF_WN + m * 4 + c] = sp[m * 4 + c] * inv;
        }
    }
    __syncthreads();

    // ---- phase 1: x = X*M (halo), Sm = clip(W@(M>0),0,1) ------------------
    const float4* Xb = reinterpret_cast<const float4*>(X)  + (size_t)b * T_;
    const float4* Mb = reinterpret_cast<const float4*>(Mk) + (size_t)b * T_;
    for (int tt = tid; tt < XLEN; tt += NTH) {
        int g = t0 - HALO + tt;
        float x0 = 0.f, x1 = 0.f, x2 = 0.f, x3 = 0.f;
        if ((unsigned)g < (unsigned)T_) {
            float4 xv = Xb[g];
            float4 mv = Mb[g];
            x0 = xv.x * mv.x; x1 = xv.y * mv.y; x2 = xv.z * mv.z; x3 = xv.w * mv.w;
            int u = tt - HALO;
            if ((unsigned)u < (unsigned)TILE) {
                float m0 = mv.x > 0.f ? 1.f : 0.f, m1 = mv.y > 0.f ? 1.f : 0.f;
                float m2 = mv.z > 0.f ? 1.f : 0.f, m3 = mv.w > 0.f ? 1.f : 0.f;
                float4 s;
                s.x = fminf(fmaxf(smem[OFF_WN+ 0]*m0 + smem[OFF_WN+ 1]*m1 + smem[OFF_WN+ 2]*m2 + smem[OFF_WN+ 3]*m3, 0.f), 1.f);
                s.y = fminf(fmaxf(smem[OFF_WN+ 4]*m0 + smem[OFF_WN+ 5]*m1 + smem[OFF_WN+ 6]*m2 + smem[OFF_WN+ 7]*m3, 0.f), 1.f);
                s.z = fminf(fmaxf(smem[OFF_WN+ 8]*m0 + smem[OFF_WN+ 9]*m1 + smem[OFF_WN+10]*m2 + smem[OFF_WN+11]*m3, 0.f), 1.f);
                s.w = fminf(fmaxf(smem[OFF_WN+12]*m0 + smem[OFF_WN+13]*m1 + smem[OFF_WN+14]*m2 + smem[OFF_WN+15]*m3, 0.f), 1.f);
                reinterpret_cast<float4*>(smem + OFF_SM)[u] = s;
            }
        }
        smem[OFF_SX + 0*XLEN + tt] = x0;
        smem[OFF_SX + 1*XLEN + tt] = x1;
        smem[OFF_SX + 2*XLEN + tt] = x2;
        smem[OFF_SX + 3*XLEN + tt] = x3;
    }
    __syncthreads();

    // ---- phase 1b: |x|, |dx| ---------------------------------------------
    for (int i = tid; i < 4 * XLEN; i += NTH) {
        int c = i / XLEN, tt = i - c * XLEN;
        int g = t0 - HALO + tt;
        float xv = smem[OFF_SX + c*XLEN + tt];
        smem[OFF_AX + c*XLEN + tt] = fabsf(xv);
        float v = 0.f;
        if (tt >= 1 && g >= 1 && g < T_)
            v = fabsf(xv - smem[OFF_SX + c*XLEN + tt - 1]);
        smem[OFF_ADX + c*XLEN + tt] = v;
    }
    __syncthreads();

    // ---- phase 2+3: S0 = W @ (.9 env + .6 burst + .2 x), zero outside [0,T)
    // Dual-j: thread handles j and j+504 -> weight loads amortized, 2x ILP.
    if (tid < 504) {
        const int ja = tid, jb = tid + 504;
        float sA0 = 0.f, sA1 = 0.f, sA2 = 0.f, sA3 = 0.f;
        float sB0 = 0.f, sB1 = 0.f, sB2 = 0.f, sB3 = 0.f;
        #pragma unroll
        for (int c = 0; c < 4; c++) {
            const float* xc = smem + OFF_SX  + c * XLEN;
            const float* ax = smem + OFF_AX  + c * XLEN;
            const float* ac = smem + OFF_ADX + c * XLEN;
            const float* we = smem + OFF_WENV + c * 25;
            const float* wb = smem + OFF_WBUR + c * 9;
            float envA = 0.f, envB = 0.f;
            #pragma unroll
            for (int k = 0; k < 25; k++) {
                float w = we[k];
                envA = fmaf(ax[ja + k], w, envA);
                envB = fmaf(ax[jb + k], w, envB);
            }
            float burA = 0.f, burB = 0.f;
            #pragma unroll
            for (int k = 0; k < 9; k++) {
                float w = wb[k];
                burA = fmaf(ac[ja + 8 + k], w, burA);
                burB = fmaf(ac[jb + 8 + k], w, burB);
            }
            float xmA = 0.9f * envA + 0.6f * burA + 0.2f * xc[ja + 12];
            float xmB = 0.9f * envB + 0.6f * burB + 0.2f * xc[jb + 12];
            float wn0 = smem[OFF_WN + 0 + c], wn1 = smem[OFF_WN + 4 + c];
            float wn2 = smem[OFF_WN + 8 + c], wn3 = smem[OFF_WN + 12 + c];
            sA0 = fmaf(wn0, xmA, sA0); sB0 = fmaf(wn0, xmB, sB0);
            sA1 = fmaf(wn1, xmA, sA1); sB1 = fmaf(wn1, xmB, sB1);
            sA2 = fmaf(wn2, xmA, sA2); sB2 = fmaf(wn2, xmB, sB2);
            sA3 = fmaf(wn3, xmA, sA3); sB3 = fmaf(wn3, xmB, sB3);
        }
        // reference zero-pads S outside [0,T)
        if ((unsigned)(t0 - 4 + ja) >= (unsigned)T_) { sA0 = sA1 = sA2 = sA3 = 0.f; }
        if ((unsigned)(t0 - 4 + jb) >= (unsigned)T_) { sB0 = sB1 = sB2 = sB3 = 0.f; }
        smem[OFF_S0 + 0*S0LEN + ja] = sA0;  smem[OFF_S0 + 0*S0LEN + jb] = sB0;
        smem[OFF_S0 + 1*S0LEN + ja] = sA1;  smem[OFF_S0 + 1*S0LEN + jb] = sB1;
        smem[OFF_S0 + 2*S0LEN + ja] = sA2;  smem[OFF_S0 + 2*S0LEN + jb] = sB2;
        smem[OFF_S0 + 3*S0LEN + ja] = sA3;  smem[OFF_S0 + 3*S0LEN + jb] = sB3;
    }
    __syncthreads();

    // ---- phase 4: dwK9+gelu, pw4x4+gelu, gate; dual-u --------------------
    if (tid < 500) {
        const int uA = tid, uB = tid + 500;
        float g1A[4], g1B[4];
        #pragma unroll
        for (int m = 0; m < 4; m++) {
            const float* s0 = smem + OFF_S0 + m * S0LEN;
            const float* wd = smem + OFF_WDW + m * 9;
            float aA = 0.f, aB = 0.f;
            #pragma unroll
            for (int k = 0; k < 9; k++) {
                float w = wd[k];
                aA = fmaf(s0[uA + k], w, aA);
                aB = fmaf(s0[uB + k], w, aB);
            }
            g1A[m] = gelu_(aA);
            g1B[m] = gelu_(aB);
        }
        float4 smA = reinterpret_cast<const float4*>(smem + OFF_SM)[uA];
        float4 smB = reinterpret_cast<const float4*>(smem + OFF_SM)[uB];
        float sArA[4] = {smA.x, smA.y, smA.z, smA.w};
        float sArB[4] = {smB.x, smB.y, smB.z, smB.w};
        const int pA = uA / 25, jjA = uA - pA * 25;
        const int pB = uB / 25, jjB = uB - pB * 25;
        #pragma unroll
        for (int o = 0; o < 4; o++) {
            float w0 = smem[OFF_WPW + o*4 + 0], w1 = smem[OFF_WPW + o*4 + 1];
            float w2 = smem[OFF_WPW + o*4 + 2], w3 = smem[OFF_WPW + o*4 + 3];
            float aA = w0*g1A[0] + w1*g1A[1] + w2*g1A[2] + w3*g1A[3];
            float aB = w0*g1B[0] + w1*g1B[1] + w2*g1B[2] + w3*g1B[3];
            smem[OFF_XS + (o * 25 + jjA) * PPAD + pA] = gelu_(aA) * sArA[o];
            smem[OFF_XS + (o * 25 + jjB) * PPAD + pB] = gelu_(aB) * sArB[o];
        }
    }
    __syncthreads();

    // ---- phase 5: patch GEMM h[p][d] = sum_k xs[k][p]*wT[k][d] -----------
    // 400 threads: 4 consecutive d (float4 w) x 4 p (2x float2 xs), f32x2 FMA.
    if (tid < 400) {
        const int d0    = (tid % 40) * 4;
        const int pbase = (tid / 40) * 4;
        unsigned long long acc[4][2];
        #pragma unroll
        for (int j = 0; j < 4; j++) { acc[j][0] = 0ull; acc[j][1] = 0ull; }
        #pragma unroll 2
        for (int k = 0; k < 100; k++) {
            const float4 w = *reinterpret_cast<const float4*>(smem + OFF_WS + k * WPADW + d0);
            const float2 xa = *reinterpret_cast<const float2*>(smem + OFF_XS + k * PPAD + pbase);
            const float2 xb = *reinterpret_cast<const float2*>(smem + OFF_XS + k * PPAD + pbase + 2);
            unsigned long long w01 = pk2_(w.x, w.y);
            unsigned long long w23 = pk2_(w.z, w.w);
            unsigned long long x0 = pk2_(xa.x, xa.x);
            unsigned long long x1 = pk2_(xa.y, xa.y);
            unsigned long long x2 = pk2_(xb.x, xb.x);
            unsigned long long x3 = pk2_(xb.y, xb.y);
            fma2_(acc[0][0], w01, x0); fma2_(acc[0][1], w23, x0);
            fma2_(acc[1][0], w01, x1); fma2_(acc[1][1], w23, x1);
            fma2_(acc[2][0], w01, x2); fma2_(acc[2][1], w23, x2);
            fma2_(acc[3][0], w01, x3); fma2_(acc[3][1], w23, x3);
        }
        #pragma unroll
        for (int j = 0; j < 4; j++) {
            float2 lo = upk2_(acc[j][0]);
            float2 hi = upk2_(acc[j][1]);
            *reinterpret_cast<float4*>(smem + OFF_H + (pbase + j) * D_ + d0) =
                make_float4(lo.x, lo.y, hi.x, hi.y);
        }
    }
    __syncthreads();

    // ---- phase 6: LayerNorm(D=160) + m_patch -----------------------------
    const int wid = tid >> 5, lane = tid & 31;
    for (int p = wid; p < NPATCH; p += NTH / 32) {
        const float* hp = smem + OFF_H + p * D_;
        float s = 0.f;
        #pragma unroll
        for (int i = 0; i < 5; i++) s += hp[lane + 32 * i];
        #pragma unroll
        for (int o = 16; o; o >>= 1) s += __shfl_xor_sync(0xffffffffu, s, o);
        float mu = s * (1.f / 160.f);
        float v = 0.f;
        #pragma unroll
        for (int i = 0; i < 5; i++) { float d = hp[lane + 32 * i] - mu; v = fmaf(d, d, v); }
        #pragma unroll
        for (int o = 16; o; o >>= 1) v += __shfl_xor_sync(0xffffffffu, v, o);
        float rstd = rsqrtf(v * (1.f / 160.f) + 1e-5f);
        const int pg = tile * NPATCH + p;
        float* oh = out_h + ((size_t)b * L_ + pg) * D_;
        #pragma unroll
        for (int i = 0; i < 5; i++) {
            int d = lane + 32 * i;
            oh[d] = (hp[d] - mu) * rstd * smem[OFF_G + d] + smem[OFF_BT + d];
        }
        int pred = 0;
        if (lane < 25) {
            float4 q = reinterpret_cast<const float4*>(smem + OFF_SM)[p * 25 + lane];
            pred = (q.x + q.y + q.z + q.w) > 0.f ? 1 : 0;
        }
        unsigned bal = __ballot_sync(0xffffffffu, pred);
        if (lane == 0) {
            int cnt = __popc(bal & 0x1ffffffu);
            out_mp[(size_t)b * L_ + pg] = ((float)cnt * (1.f / 25.f) > 0.1f) ? 1.f : 0.f;
        }
    }
}

extern "C" void kernel_launch(void* const* d_in, const int* in_sizes, int n_in,
                              void* d_out, int out_size) {
    const float* X      = (const float*)d_in[0];
    const float* M      = (const float*)d_in[1];
    const float* w_env  = (const float*)d_in[2];
    const float* w_bur  = (const float*)d_in[3];
    const float* syn    = (const float*)d_in[4];
    const float* w_dw   = (const float*)d_in[5];
    const float* w_pw   = (const float*)d_in[6];
    const float* w_proj = (const float*)d_in[7];
    const float* gam    = (const float*)d_in[8];
    const float* bet    = (const float*)d_in[9];

    float* out_h  = (float*)d_out;
    float* out_mp = out_h + (size_t)B_ * L_ * D_;

    cudaFuncSetAttribute(emg_fused_kernel,
                         cudaFuncAttributeMaxDynamicSharedMemorySize,
                         SMEM_FLOATS * (int)sizeof(float));

    emg_fused_kernel<<<B_ * TPB, NTH, SMEM_FLOATS * (int)sizeof(float)>>>(
        X, M, w_env, w_bur, syn, w_dw, w_pw, w_proj, gam, bet, out_h, out_mp);
}